// round 9
// baseline (speedup 1.0000x reference)
#include <cuda_runtime.h>
#include <math.h>

// ---------------- constants ----------------
#define BB 4
#define HFD 128
#define WFD 128
#define KPRE 2000
#define KOUT 500

typedef unsigned long long u64;

// ---------------- scratch (device globals; no allocation allowed) ----------------
__device__ __align__(16) float g_x1[(size_t)4 * 256 * 256 * 64];       // conv1 out
__device__ __align__(16) float g_feat[(size_t)4 * 128 * 128 * 256];    // conv2 out
__device__ __align__(16) float g_segr[(size_t)4 * 128 * 128 * 32];     // reduced seg feats
__device__ __align__(16) float g_scores[4 * 16384];
__device__ __align__(16) float g_reg[4 * 16384 * 2];
__device__ __align__(16) float g_topsc[4 * KPRE];
__device__ __align__(16) float g_locs[4 * KPRE * 2];
__device__ __align__(16) unsigned g_sup[(size_t)4 * KPRE * 64];        // suppression bitmatrix
__device__ int g_sel[4 * KOUT];
__device__ int g_nsel[4];
__device__ int g_tl[4 * KOUT * 2];
__device__ __align__(16) float g_instfull[4 * 128 * 128];
__device__ __align__(16) float g_acc1[(size_t)4 * 128 * 128 * 32];     // instfull pre-bias acc

// transposed/interleaved weights for f32x2 (built per launch by tiny kernels)
__device__ __align__(16) float g_wt_seg[256 * 256];   // [ci2][c][2]
__device__ __align__(16) float g_wt_r[256 * 32];      // [ci2][co][2]
__device__ __align__(16) float g_wt2[9 * 64 * 256];   // [tap][ci2][co][2]

__device__ __forceinline__ float sigmoidf(float z) { return 1.f / (1.f + expf(-z)); }

// ---- packed f32x2 helpers (u64 as b64 carrier of two floats; "l" constraints) ----
__device__ __forceinline__ void ffma2(u64& acc, u64 a, u64 b) {
    asm("fma.rn.f32x2 %0, %1, %2, %0;" : "+l"(acc) : "l"(a), "l"(b));
}
__device__ __forceinline__ u64 pack2(float v) {
    u64 d; asm("mov.b64 %0, {%1, %1};" : "=l"(d) : "f"(v)); return d;
}
__device__ __forceinline__ float f2sum(u64 a) {
    float lo, hi; asm("mov.b64 {%0, %1}, %2;" : "=f"(lo), "=f"(hi) : "l"(a));
    return lo + hi;
}
__device__ __forceinline__ float f2sum2(u64 a, u64 b) {
    float alo, ahi, blo, bhi;
    asm("mov.b64 {%0, %1}, %2;" : "=f"(alo), "=f"(ahi) : "l"(a));
    asm("mov.b64 {%0, %1}, %2;" : "=f"(blo), "=f"(bhi) : "l"(b));
    return (alo + ahi) + (blo + bhi);
}
__device__ __forceinline__ void f2unpack(u64 a, float& lo, float& hi) {
    asm("mov.b64 {%0, %1}, %2;" : "=f"(lo), "=f"(hi) : "l"(a));
}

// ---------------- weight transpose kernels ----------------
__global__ void tr_seg_kernel(const float* __restrict__ wseg) {
    int idx = blockIdx.x * 256 + threadIdx.x;     // 65536
    int k = idx & 1, c = (idx >> 1) & 255, ci2 = idx >> 9;
    g_wt_seg[idx] = wseg[(2 * ci2 + k) * 256 + c];
}
__global__ void tr_r_kernel(const float* __restrict__ wr) {
    int idx = blockIdx.x * 256 + threadIdx.x;     // 8192
    int k = idx & 1, co = (idx >> 1) & 31, ci2 = idx >> 6;
    g_wt_r[idx] = wr[(2 * ci2 + k) * 32 + co];
}
__global__ void tr_w2_kernel(const float* __restrict__ w2) {
    int idx = blockIdx.x * 256 + threadIdx.x;     // 147456
    int k = idx & 1, co = (idx >> 1) & 255;
    int r = idx >> 9; int ci2 = r & 31; int tap = r >> 5;
    g_wt2[idx] = w2[(tap * 64 + 2 * ci2 + k) * 256 + co];
}

// ---------------- conv1: 3x3 s2, 3->64, relu (SAME => iy=2y+ky, pad_lo=0) ----------------
// block: 8x8 output tile, 256 thr = 32 co-pairs x 8 rows; co-pair packed FFMA2.
__global__ void conv1_kernel(const float* __restrict__ img, const float* __restrict__ w1,
                             const float* __restrict__ b1) {
    __shared__ __align__(16) float smimg[17 * 17 * 3 + 1];   // rows 2y0..2y0+16, cols 2x0..2x0+16
    __shared__ __align__(16) float wsh[27 * 64];
    __shared__ __align__(16) float sbias[64];
    int x0 = blockIdx.x * 8, y0 = blockIdx.y * 8, b = blockIdx.z;
    int t = threadIdx.x;
    for (int e = t; e < 17 * 17 * 3; e += 256) {
        int r = e / 51, rem = e % 51, c = rem / 3, ci = rem % 3;
        int iy = 2 * y0 + r, ix = 2 * x0 + c;
        smimg[e] = (iy < 512 && ix < 512) ? __ldg(img + ((size_t)(b * 512 + iy) * 512 + ix) * 3 + ci) : 0.f;
    }
    for (int e = t; e < 27 * 64; e += 256) wsh[e] = __ldg(w1 + e);
    if (t < 64) sbias[t] = __ldg(b1 + t);
    __syncthreads();
    int copair = t & 31, py = t >> 5;
    int c0 = copair * 2;
    u64 acc[8];
#pragma unroll
    for (int p = 0; p < 8; p++) acc[p] = 0ull;
#pragma unroll
    for (int ky = 0; ky < 3; ky++) {
        int rowb = (2 * py + ky) * 51;
#pragma unroll
        for (int kx = 0; kx < 3; kx++) {
#pragma unroll
            for (int ci = 0; ci < 3; ci++) {
                u64 w2 = *(const u64*)(wsh + ((ky * 3 + kx) * 3 + ci) * 64 + c0);
                int off = rowb + kx * 3 + ci;
#pragma unroll
                for (int p = 0; p < 8; p++) {
                    u64 vv = pack2(smimg[off + p * 6]);
                    ffma2(acc[p], vv, w2);
                }
            }
        }
    }
    float2 bb = *(const float2*)(sbias + c0);
    int y = y0 + py;
#pragma unroll
    for (int p = 0; p < 8; p++) {
        float lo, hi; f2unpack(acc[p], lo, hi);
        float2 o;
        o.x = fmaxf(lo + bb.x, 0.f);
        o.y = fmaxf(hi + bb.y, 0.f);
        *(float2*)(g_x1 + ((size_t)(b * 256 + y) * 256 + (x0 + p)) * 64 + c0) = o;
    }
}

// ---------------- conv2: 3x3 s2, 64->256, relu; ci-pair packed ----------------
// NOTE: no min-blocks bound — the u64 accumulator file (~120 regs) must not be
// capped at 128 regs or ptxas spills to local memory in the inner loop.
__global__ void __launch_bounds__(256) conv2_kernel(const float* __restrict__ b2) {
    __shared__ __align__(16) float sm[9 * 17 * 64];  // input tile (rows 2y0..2y0+8, cols 2x0..2x0+16)
    int x0 = blockIdx.x * 8, y0 = blockIdx.y * 4, b = blockIdx.z;
    int t = threadIdx.x;
    for (int e = t; e < 9 * 17 * 64; e += 256) {
        int ci = e & 63; int rc = e >> 6; int c = rc % 17; int r = rc / 17;
        int iy = 2 * y0 + r, ix = 2 * x0 + c;
        float v = 0.f;
        if (iy < 256 && ix < 256) v = g_x1[((size_t)(b * 256 + iy) * 256 + ix) * 64 + ci];
        sm[e] = v;
    }
    __syncthreads();
    int co4 = t & 63, ry = t >> 6;
    u64 acc[8][4];
#pragma unroll
    for (int p = 0; p < 8; p++)
#pragma unroll
        for (int j = 0; j < 4; j++) acc[p][j] = 0ull;
    const u64* wt2d = (const u64*)g_wt2;
#pragma unroll
    for (int ky = 0; ky < 3; ky++) {
        int r = 2 * ry + ky;
#pragma unroll
        for (int kx = 0; kx < 3; kx++) {
            const float* sbase = sm + (r * 17 + kx) * 64;
            const u64* wb = wt2d + (size_t)((ky * 3 + kx) * 32) * 256 + co4 * 4;
            for (int ci2 = 0; ci2 < 32; ci2++) {
                u64 v[8];
#pragma unroll
                for (int p = 0; p < 8; p++) v[p] = *(const u64*)(sbase + p * 128 + 2 * ci2);
                ulonglong2 wA = *(const ulonglong2*)(wb + (size_t)ci2 * 256);
                ulonglong2 wB = *(const ulonglong2*)(wb + (size_t)ci2 * 256 + 2);
#pragma unroll
                for (int p = 0; p < 8; p++) {
                    ffma2(acc[p][0], v[p], wA.x);
                    ffma2(acc[p][1], v[p], wA.y);
                    ffma2(acc[p][2], v[p], wB.x);
                    ffma2(acc[p][3], v[p], wB.y);
                }
            }
        }
    }
    int y = y0 + ry;
    float4 bb = *(const float4*)(b2 + co4 * 4);
#pragma unroll
    for (int p = 0; p < 8; p++) {
        float4 o;
        o.x = fmaxf(f2sum(acc[p][0]) + bb.x, 0.f);
        o.y = fmaxf(f2sum(acc[p][1]) + bb.y, 0.f);
        o.z = fmaxf(f2sum(acc[p][2]) + bb.z, 0.f);
        o.w = fmaxf(f2sum(acc[p][3]) + bb.w, 0.f);
        *(float4*)(g_feat + ((size_t)(b * 128 + y) * 128 + (x0 + p)) * 256 + co4 * 4) = o;
    }
}

// ---------------- detection heads: scores (sigmoid) + reg, both 3x3 s1 SAME (centered) ----------------
__global__ void heads_kernel(const float* __restrict__ wsc, const float* __restrict__ bsc,
                             const float* __restrict__ wrg, const float* __restrict__ brg) {
    int b = blockIdx.y;
    int warp = threadIdx.x >> 5, lane = threadIdx.x & 31;
    int p = blockIdx.x * 8 + warp;
    int y = p >> 7, x = p & 127;
    float as = 0.f, ay = 0.f, ax = 0.f;
    for (int e = lane; e < 2304; e += 32) {
        int ky = e / 768; int rem = e - ky * 768; int kx = rem >> 8; int ci = rem & 255;
        int iy = y + ky - 1, ix = x + kx - 1;
        if ((unsigned)iy < 128u && (unsigned)ix < 128u) {
            float f = __ldg(g_feat + ((size_t)(b * 128 + iy) * 128 + ix) * 256 + ci);
            as += f * __ldg(wsc + e);
            ay += f * __ldg(wrg + 2 * e);
            ax += f * __ldg(wrg + 2 * e + 1);
        }
    }
#pragma unroll
    for (int o = 16; o > 0; o >>= 1) {
        as += __shfl_down_sync(~0u, as, o);
        ay += __shfl_down_sync(~0u, ay, o);
        ax += __shfl_down_sync(~0u, ax, o);
    }
    if (lane == 0) {
        g_scores[b * 16384 + p] = sigmoidf(as + __ldg(bsc));
        g_reg[(b * 16384 + p) * 2]     = ay + __ldg(brg);
        g_reg[(b * 16384 + p) * 2 + 1] = ax + __ldg(brg + 1);
    }
}

// ---------------- fused seg (1x1 256->256 relu) + segr (1x1 256->32 relu); ci-pair packed ----------------
// NOTE: no min-blocks bound (same spill-avoidance reasoning as conv2).
__global__ void __launch_bounds__(256) segseg_kernel(const float* __restrict__ bseg,
                                                     const float* __restrict__ br) {
    __shared__ __align__(16) float sf[32 * 256];   // 32 pixels; reused as stage1 output
    int b = blockIdx.y; int p0 = blockIdx.x * 32; int t = threadIdx.x;
    {
        const float4* src = (const float4*)(g_feat + ((size_t)b * 16384 + p0) * 256);
        float4* dst4 = (float4*)sf;
        for (int e = t; e < 2048; e += 256) dst4[e] = src[e];
    }
    __syncthreads();
    // stage1: tid -> 64 channel-groups (4 ch) x 4 pixel-groups (8 px)
    int cg = t & 63, pg = t >> 6;
    int c0 = cg * 4;
    const float* sbase = sf + pg * 8 * 256;
    u64 acc[8][4];
#pragma unroll
    for (int p = 0; p < 8; p++)
#pragma unroll
        for (int j = 0; j < 4; j++) acc[p][j] = 0ull;
    const u64* wtd = (const u64*)g_wt_seg + c0;
    for (int ci2 = 0; ci2 < 128; ci2++) {
        u64 v[8];
#pragma unroll
        for (int p = 0; p < 8; p++) v[p] = *(const u64*)(sbase + p * 256 + 2 * ci2);
        ulonglong2 wA = *(const ulonglong2*)(wtd + (size_t)ci2 * 256);
        ulonglong2 wB = *(const ulonglong2*)(wtd + (size_t)ci2 * 256 + 2);
#pragma unroll
        for (int p = 0; p < 8; p++) {
            ffma2(acc[p][0], v[p], wA.x);
            ffma2(acc[p][1], v[p], wA.y);
            ffma2(acc[p][2], v[p], wB.x);
            ffma2(acc[p][3], v[p], wB.y);
        }
    }
    float bs[4];
#pragma unroll
    for (int j = 0; j < 4; j++) bs[j] = __ldg(bseg + c0 + j);
    __syncthreads();   // all sf reads done
#pragma unroll
    for (int p = 0; p < 8; p++) {
        float4 o;
        o.x = fmaxf(f2sum(acc[p][0]) + bs[0], 0.f);
        o.y = fmaxf(f2sum(acc[p][1]) + bs[1], 0.f);
        o.z = fmaxf(f2sum(acc[p][2]) + bs[2], 0.f);
        o.w = fmaxf(f2sum(acc[p][3]) + bs[3], 0.f);
        *(float4*)(sf + (pg * 8 + p) * 256 + c0) = o;
    }
    __syncthreads();
    // stage2: tid -> 32 co x 8 pixel-groups (4 px each)
    int co = t & 31, pg2 = t >> 5;
    u64 a2[4];
#pragma unroll
    for (int q = 0; q < 4; q++) a2[q] = 0ull;
    const u64* wrd = (const u64*)g_wt_r + co;
    const float* s2 = sf + pg2 * 4 * 256;
    for (int ci2 = 0; ci2 < 128; ci2++) {
        u64 w = wrd[ci2 * 32];
#pragma unroll
        for (int q = 0; q < 4; q++)
            ffma2(a2[q], *(const u64*)(s2 + q * 256 + 2 * ci2), w);
    }
    float bc = __ldg(br + co);
#pragma unroll
    for (int q = 0; q < 4; q++)
        g_segr[((size_t)b * 16384 + p0 + pg2 * 4 + q) * 32 + co] = fmaxf(f2sum(a2[q]) + bc, 0.f);
}

// ---------------- top-K_PRE: full bitonic sort of 16384 packed keys per batch ----------------
__global__ void topk_kernel() {
    extern __shared__ unsigned long long sk[];
    int b = blockIdx.x, t = threadIdx.x;
    for (int e = t; e < 16384; e += 1024) {
        unsigned fb = __float_as_uint(g_scores[b * 16384 + e]);
        sk[e] = ((unsigned long long)fb << 32) | (unsigned)(16383 - e);
    }
    for (unsigned k = 2; k <= 16384u; k <<= 1)
        for (unsigned j = k >> 1; j > 0; j >>= 1) {
            __syncthreads();
            for (unsigned e = t; e < 16384; e += 1024) {
                unsigned l = e ^ j;
                if (l > e) {
                    unsigned long long A = sk[e], C = sk[l];
                    bool desc = ((e & k) == 0);
                    if ((A < C) == desc) { sk[e] = C; sk[l] = A; }
                }
            }
        }
    __syncthreads();
    for (int e = t; e < KPRE; e += 1024) {
        unsigned long long key = sk[e];
        float s = __uint_as_float((unsigned)(key >> 32));
        int idx = 16383 - (int)(unsigned)(key & 0xFFFFFFFFu);
        g_topsc[b * KPRE + e] = s;
        float yy = (float)(idx >> 7), xx = (float)(idx & 127);
        g_locs[(b * KPRE + e) * 2]     = yy + 0.5f + g_reg[(b * 16384 + idx) * 2];
        g_locs[(b * KPRE + e) * 2 + 1] = xx + 0.5f + g_reg[(b * 16384 + idx) * 2 + 1];
    }
}

// ---------------- suppression bitmatrix: sup[i] bit j <=> dist(i,j) <= 1.1 ----------------
__global__ void sup_kernel() {
    int i = blockIdx.x, b = blockIdx.y, w = threadIdx.x;   // 64 threads
    float ly = g_locs[(b * KPRE + i) * 2], lx = g_locs[(b * KPRE + i) * 2 + 1];
    unsigned bits = 0;
    if (w < 63) {
        int j0 = w * 32;
#pragma unroll 4
        for (int u = 0; u < 32; u++) {
            int j = j0 + u;
            if (j < KPRE) {
                float dy = ly - g_locs[(b * KPRE + j) * 2];
                float dx = lx - g_locs[(b * KPRE + j) * 2 + 1];
                if (sqrtf(dy * dy + dx * dx) <= 1.1f) bits |= (1u << u);
            }
        }
    }
    g_sup[((size_t)(b * KPRE) + i) * 64 + w] = bits;
}

// ---------------- sequential greedy NMS scan (single warp/batch, deep prefetch) ----------------
__global__ void nms_scan_kernel() {
    int b = blockIdx.x, lane = threadIdx.x;   // 32 threads
    __shared__ unsigned ssup[64];
    __shared__ int slist[KOUT];
    ssup[lane] = 0; ssup[lane + 32] = 0;
    __syncwarp();
    const unsigned* base = g_sup + (size_t)b * KPRE * 64;
    unsigned ca[8], cb[8], na[8], nb[8];
#pragma unroll
    for (int u = 0; u < 8; u++) {
        ca[u] = base[(size_t)u * 64 + lane];
        cb[u] = (lane < 31) ? base[(size_t)u * 64 + 32 + lane] : 0u;
    }
    int cnt = 0;
    for (int ch = 0; ch < KPRE; ch += 8) {
        if (ch + 8 < KPRE) {
#pragma unroll
            for (int u = 0; u < 8; u++) {
                int i = ch + 8 + u;
                na[u] = base[(size_t)i * 64 + lane];
                nb[u] = (lane < 31) ? base[(size_t)i * 64 + 32 + lane] : 0u;
            }
        }
#pragma unroll
        for (int u = 0; u < 8; u++) {
            int i = ch + u;
            bool kp = ((ssup[i >> 5] >> (i & 31)) & 1u) == 0u;
            if (kp) {
                ssup[lane] |= ca[u];
                if (lane < 31) ssup[32 + lane] |= cb[u];
                if (lane == 0) { if (cnt < KOUT) slist[cnt] = i; cnt++; }
            }
            __syncwarp();
        }
#pragma unroll
        for (int u = 0; u < 8; u++) { ca[u] = na[u]; cb[u] = nb[u]; }
    }
    cnt = __shfl_sync(~0u, cnt, 0);
    if (lane == 0) g_nsel[b] = cnt;
    __syncwarp();
    int n = cnt < KOUT ? cnt : KOUT;
    for (int k = lane; k < n; k += 32) g_sel[b * KOUT + k] = slist[k];
}

// ---------------- selection: sel_s, pix outputs + crop top-lefts ----------------
__global__ void select_kernel(float* __restrict__ out) {
    int b = blockIdx.x; int k = threadIdx.x;
    if (k >= KOUT) return;
    int n = g_nsel[b]; if (n > KOUT) n = KOUT;
    bool valid = (k < n);
    float s = -1.f, ly = 0.f, lx = 0.f;
    if (valid) {
        int i = g_sel[b * KOUT + k];
        s  = g_topsc[b * KPRE + i];
        ly = g_locs[(b * KPRE + i) * 2];
        lx = g_locs[(b * KPRE + i) * 2 + 1];
    }
    float cy, cx;
    int o = b * KOUT + k;
    if (valid) {
        out[o] = s;
        out[2000 + o * 2]     = ly * 4.f;
        out[2000 + o * 2 + 1] = lx * 4.f;
        cy = ly; cx = lx;
    } else {
        out[o] = -1.f;
        out[2000 + o * 2] = -1.f;
        out[2000 + o * 2 + 1] = -1.f;
        cy = -0.25f; cx = -0.25f;    // pix=-1 -> (-1/512)*128
    }
    int ty = (int)rintf(cy) - 16; ty = min(max(ty, 0), 96);
    int tx = (int)rintf(cx) - 16; tx = min(max(tx, 0), 96);
    g_tl[o * 2] = ty; g_tl[o * 2 + 1] = tx;
}

// ---------------- inst_full: global 3x3 conv(32->32) over segr; stores pre-bias acc + final sigmoid ----------------
__global__ void instfull_kernel(const float* __restrict__ wp1, const float* __restrict__ bp1v,
                                const float* __restrict__ wp2, const float* __restrict__ bp2v) {
    __shared__ __align__(16) float ws2[9216];     // [tap][ci2][co][2] interleaved ci-pairs
    __shared__ __align__(16) float sb1[32];
    __shared__ __align__(16) float sw2[32];
    int t = threadIdx.x;
    for (int e = t; e < 9216; e += 256) {
        int k = e & 1, co = (e >> 1) & 31, r = e >> 6;
        int ci2 = r & 15, tap = r >> 4;
        ws2[e] = __ldg(wp1 + (tap * 32 + 2 * ci2 + k) * 32 + co);
    }
    if (t < 32) { sb1[t] = __ldg(bp1v + t); sw2[t] = __ldg(wp2 + t); }
    __syncthreads();
    int b = blockIdx.y;
    int warp = t >> 5, lane = t & 31;
    int p = blockIdx.x * 8 + warp;
    int y = p >> 7, x = p & 127;
    const u64* wsd = (const u64*)ws2;
    u64 accA = 0ull, accB = 0ull;      // two chains to break FFMA2 latency serialization
#pragma unroll
    for (int dy = -1; dy <= 1; dy++) {
        int iy = y + dy; if ((unsigned)iy >= 128u) continue;
#pragma unroll
        for (int dx = -1; dx <= 1; dx++) {
            int ix = x + dx; if ((unsigned)ix >= 128u) continue;
            const float* sp = g_segr + ((size_t)(b * 128 + iy) * 128 + ix) * 32;
            const u64* wb = wsd + (((dy + 1) * 3 + (dx + 1)) * 16) * 32 + lane;
#pragma unroll
            for (int ci2 = 0; ci2 < 16; ci2 += 2) {
                ffma2(accA, *(const u64*)(sp + 2 * ci2), wb[ci2 * 32]);
                ffma2(accB, *(const u64*)(sp + 2 * ci2 + 2), wb[(ci2 + 1) * 32]);
            }
        }
    }
    float a = f2sum2(accA, accB);
    g_acc1[((size_t)(b * 128 + y) * 128 + x) * 32 + lane] = a;
    float h = fmaxf(a + sb1[lane], 0.f);
    float v = h * sw2[lane];
#pragma unroll
    for (int o = 16; o > 0; o >>= 1) v += __shfl_down_sync(~0u, v, o);
    if (lane == 0) g_instfull[(size_t)(b * 128 + y) * 128 + x] = sigmoidf(v + __ldg(bp2v));
}

// ---------------- per-patch: gather interior; border via acc1 subtraction ----------------
__global__ void patch_kernel(const float* __restrict__ wp1, const float* __restrict__ bp1v,
                             const float* __restrict__ wp2, const float* __restrict__ bp2v,
                             float* __restrict__ out) {
    __shared__ __align__(16) float ws2[9216];
    __shared__ __align__(16) float sb1[32];
    __shared__ __align__(16) float sw2[32];
    int blk = blockIdx.x; int b = blk / KOUT, k = blk % KOUT;
    int t = threadIdx.x;
    for (int e = t; e < 9216; e += 256) {
        int kk = e & 1, co = (e >> 1) & 31, r = e >> 6;
        int ci2 = r & 15, tap = r >> 4;
        ws2[e] = __ldg(wp1 + (tap * 32 + 2 * ci2 + kk) * 32 + co);
    }
    if (t < 32) { sb1[t] = __ldg(bp1v + t); sw2[t] = __ldg(wp2 + t); }
    int ty = g_tl[(b * KOUT + k) * 2], tx = g_tl[(b * KOUT + k) * 2 + 1];
    float* obase = out + 6000 + ((size_t)(b * KOUT + k)) * 1024;
    for (int e = t; e < 1024; e += 256) {
        int py = e >> 5, px = e & 31;
        if (py >= 1 && py <= 30 && px >= 1 && px <= 30)
            obase[e] = g_instfull[(size_t)(b * 128 + ty + py) * 128 + tx + px];
    }
    __syncthreads();
    float bp2s = __ldg(bp2v);
    int warp = t >> 5, lane = t & 31;
    const u64* wsd = (const u64*)ws2;
    for (int bp = warp; bp < 124; bp += 8) {
        int py, px;
        if (bp < 32)      { py = 0;       px = bp; }
        else if (bp < 64) { py = 31;      px = bp - 32; }
        else if (bp < 94) { py = bp - 63; px = 0; }
        else              { py = bp - 93; px = 31; }
        int gy = ty + py, gx = tx + px;
        u64 corr = 0ull;
#pragma unroll
        for (int dy = -1; dy <= 1; dy++) {
            int ly = py + dy, yy = gy + dy;
#pragma unroll
            for (int dx = -1; dx <= 1; dx++) {
                int lx = px + dx, xx = gx + dx;
                bool outside_patch = ((unsigned)ly >= 32u) || ((unsigned)lx >= 32u);
                bool inside_global = ((unsigned)yy < 128u) && ((unsigned)xx < 128u);
                if (outside_patch && inside_global) {
                    const float* sp = g_segr + ((size_t)(b * 128 + yy) * 128 + xx) * 32;
                    const u64* wb = wsd + (((dy + 1) * 3 + (dx + 1)) * 16) * 32 + lane;
#pragma unroll
                    for (int ci2 = 0; ci2 < 16; ci2++)
                        ffma2(corr, *(const u64*)(sp + 2 * ci2), wb[ci2 * 32]);
                }
            }
        }
        float a = g_acc1[((size_t)(b * 128 + gy) * 128 + gx) * 32 + lane] - f2sum(corr);
        float h = fmaxf(a + sb1[lane], 0.f);
        float v = h * sw2[lane];
#pragma unroll
        for (int o = 16; o > 0; o >>= 1) v += __shfl_down_sync(~0u, v, o);
        if (lane == 0) obase[py * 32 + px] = sigmoidf(v + bp2s);
    }
}

// ---------------- launch ----------------
extern "C" void kernel_launch(void* const* d_in, const int* in_sizes, int n_in,
                              void* d_out, int out_size) {
    const float* image = (const float*)d_in[0];
    const float* w1   = (const float*)d_in[1];
    const float* b1   = (const float*)d_in[2];
    const float* w2   = (const float*)d_in[3];
    const float* b2   = (const float*)d_in[4];
    const float* wseg = (const float*)d_in[5];
    const float* bseg = (const float*)d_in[6];
    const float* wsc  = (const float*)d_in[7];
    const float* bsc  = (const float*)d_in[8];
    const float* wrg  = (const float*)d_in[9];
    const float* brg  = (const float*)d_in[10];
    const float* wr   = (const float*)d_in[11];
    const float* br   = (const float*)d_in[12];
    const float* wp1  = (const float*)d_in[13];
    const float* bp1  = (const float*)d_in[14];
    const float* wp2  = (const float*)d_in[15];
    const float* bp2  = (const float*)d_in[16];
    float* out = (float*)d_out;

    cudaFuncSetAttribute(topk_kernel, cudaFuncAttributeMaxDynamicSharedMemorySize, 131072);

    tr_seg_kernel<<<256, 256>>>(wseg);
    tr_r_kernel<<<32, 256>>>(wr);
    tr_w2_kernel<<<576, 256>>>(w2);

    conv1_kernel<<<dim3(32, 32, 4), 256>>>(image, w1, b1);
    conv2_kernel<<<dim3(16, 32, 4), 256>>>(b2);
    heads_kernel<<<dim3(2048, 4), 256>>>(wsc, bsc, wrg, brg);
    segseg_kernel<<<dim3(512, 4), 256>>>(bseg, br);
    topk_kernel<<<4, 1024, 131072>>>();
    sup_kernel<<<dim3(KPRE, 4), 64>>>();
    nms_scan_kernel<<<4, 32>>>();
    select_kernel<<<4, 512>>>(out);
    instfull_kernel<<<dim3(2048, 4), 256>>>(wp1, bp1, wp2, bp2);
    patch_kernel<<<BB * KOUT, 256>>>(wp1, bp1, wp2, bp2, out);
}

// round 10
// speedup vs baseline: 1.1248x; 1.1248x over previous
#include <cuda_runtime.h>
#include <math.h>

// ---------------- constants ----------------
#define BB 4
#define HFD 128
#define WFD 128
#define KPRE 2000
#define KOUT 500

typedef unsigned long long u64;

// ---------------- scratch (device globals; no allocation allowed) ----------------
__device__ __align__(16) float g_x1[(size_t)4 * 256 * 256 * 64];       // conv1 out
__device__ __align__(16) float g_feat[(size_t)4 * 128 * 128 * 256];    // conv2 out
__device__ __align__(16) float g_segr[(size_t)4 * 128 * 128 * 32];     // reduced seg feats
__device__ __align__(16) float g_scores[4 * 16384];
__device__ __align__(16) float g_reg[4 * 16384 * 2];
__device__ __align__(16) float g_topsc[4 * KPRE];
__device__ __align__(16) float g_locs[4 * KPRE * 2];
__device__ __align__(16) unsigned g_sup[(size_t)4 * KPRE * 64];        // suppression bitmatrix
__device__ int g_sel[4 * KOUT];
__device__ int g_nsel[4];
__device__ int g_tl[4 * KOUT * 2];
__device__ __align__(16) float g_instfull[4 * 128 * 128];
__device__ __align__(16) float g_acc1[(size_t)4 * 128 * 128 * 32];     // instfull pre-bias acc

// transposed/interleaved weights for f32x2 (built per launch by tiny kernels)
__device__ __align__(16) float g_wt_seg[256 * 256];   // [ci2][c][2]
__device__ __align__(16) float g_wt_r[256 * 32];      // [ci2][co][2]
__device__ __align__(16) float g_wt2[9 * 64 * 256];   // [tap][ci2][co][2]
__device__ __align__(16) float g_wt_h[9 * 128 * 6];   // [tap][ci2][{sc0,sc1,rgy0,rgy1,rgx0,rgx1}]
__device__ __align__(16) float g_wt_p1[9 * 16 * 64];  // [tap][ci2][co][2]

__device__ __forceinline__ float sigmoidf(float z) { return 1.f / (1.f + expf(-z)); }

// ---- packed f32x2 helpers (u64 as b64 carrier of two floats; "l" constraints) ----
__device__ __forceinline__ void ffma2(u64& acc, u64 a, u64 b) {
    asm("fma.rn.f32x2 %0, %1, %2, %0;" : "+l"(acc) : "l"(a), "l"(b));
}
__device__ __forceinline__ u64 pack2(float v) {
    u64 d; asm("mov.b64 %0, {%1, %1};" : "=l"(d) : "f"(v)); return d;
}
__device__ __forceinline__ float f2sum(u64 a) {
    float lo, hi; asm("mov.b64 {%0, %1}, %2;" : "=f"(lo), "=f"(hi) : "l"(a));
    return lo + hi;
}
__device__ __forceinline__ float f2sum2(u64 a, u64 b) {
    float alo, ahi, blo, bhi;
    asm("mov.b64 {%0, %1}, %2;" : "=f"(alo), "=f"(ahi) : "l"(a));
    asm("mov.b64 {%0, %1}, %2;" : "=f"(blo), "=f"(bhi) : "l"(b));
    return (alo + ahi) + (blo + bhi);
}
__device__ __forceinline__ void f2unpack(u64 a, float& lo, float& hi) {
    asm("mov.b64 {%0, %1}, %2;" : "=f"(lo), "=f"(hi) : "l"(a));
}

// ---------------- weight transpose kernels ----------------
__global__ void tr_seg_kernel(const float* __restrict__ wseg) {
    int idx = blockIdx.x * 256 + threadIdx.x;     // 65536
    int k = idx & 1, c = (idx >> 1) & 255, ci2 = idx >> 9;
    g_wt_seg[idx] = wseg[(2 * ci2 + k) * 256 + c];
}
__global__ void tr_r_kernel(const float* __restrict__ wr) {
    int idx = blockIdx.x * 256 + threadIdx.x;     // 8192
    int k = idx & 1, co = (idx >> 1) & 31, ci2 = idx >> 6;
    g_wt_r[idx] = wr[(2 * ci2 + k) * 32 + co];
}
__global__ void tr_w2_kernel(const float* __restrict__ w2) {
    int idx = blockIdx.x * 256 + threadIdx.x;     // 147456
    int k = idx & 1, co = (idx >> 1) & 255;
    int r = idx >> 9; int ci2 = r & 31; int tap = r >> 5;
    g_wt2[idx] = w2[(tap * 64 + 2 * ci2 + k) * 256 + co];
}
__global__ void tr_h_kernel(const float* __restrict__ wsc, const float* __restrict__ wrg) {
    int idx = blockIdx.x * 256 + threadIdx.x;     // 6912
    int comp = idx % 6; int entry = idx / 6;
    int ci2 = entry & 127, tap = entry >> 7;
    int e0 = tap * 256 + 2 * ci2;
    float v;
    switch (comp) {
        case 0: v = wsc[e0]; break;
        case 1: v = wsc[e0 + 1]; break;
        case 2: v = wrg[e0 * 2]; break;
        case 3: v = wrg[(e0 + 1) * 2]; break;
        case 4: v = wrg[e0 * 2 + 1]; break;
        default: v = wrg[(e0 + 1) * 2 + 1]; break;
    }
    g_wt_h[idx] = v;
}
__global__ void tr_p1_kernel(const float* __restrict__ wp1) {
    int e = blockIdx.x * 256 + threadIdx.x;       // 9216
    int kk = e & 1, co = (e >> 1) & 31, r = e >> 6;
    int ci2 = r & 15, tap = r >> 4;
    g_wt_p1[e] = wp1[(tap * 32 + 2 * ci2 + kk) * 32 + co];
}

// ---------------- conv1: 3x3 s2, 3->64, relu (SAME => iy=2y+ky, pad_lo=0) ----------------
__global__ void conv1_kernel(const float* __restrict__ img, const float* __restrict__ w1,
                             const float* __restrict__ b1) {
    __shared__ __align__(16) float smimg[17 * 17 * 3 + 1];
    __shared__ __align__(16) float wsh[27 * 64];
    __shared__ __align__(16) float sbias[64];
    int x0 = blockIdx.x * 8, y0 = blockIdx.y * 8, b = blockIdx.z;
    int t = threadIdx.x;
    for (int e = t; e < 17 * 17 * 3; e += 256) {
        int r = e / 51, rem = e % 51, c = rem / 3, ci = rem % 3;
        int iy = 2 * y0 + r, ix = 2 * x0 + c;
        smimg[e] = (iy < 512 && ix < 512) ? __ldg(img + ((size_t)(b * 512 + iy) * 512 + ix) * 3 + ci) : 0.f;
    }
    for (int e = t; e < 27 * 64; e += 256) wsh[e] = __ldg(w1 + e);
    if (t < 64) sbias[t] = __ldg(b1 + t);
    __syncthreads();
    int copair = t & 31, py = t >> 5;
    int c0 = copair * 2;
    u64 acc[8];
#pragma unroll
    for (int p = 0; p < 8; p++) acc[p] = 0ull;
#pragma unroll
    for (int ky = 0; ky < 3; ky++) {
        int rowb = (2 * py + ky) * 51;
#pragma unroll
        for (int kx = 0; kx < 3; kx++) {
#pragma unroll
            for (int ci = 0; ci < 3; ci++) {
                u64 w2 = *(const u64*)(wsh + ((ky * 3 + kx) * 3 + ci) * 64 + c0);
                int off = rowb + kx * 3 + ci;
#pragma unroll
                for (int p = 0; p < 8; p++) {
                    u64 vv = pack2(smimg[off + p * 6]);
                    ffma2(acc[p], vv, w2);
                }
            }
        }
    }
    float2 bb = *(const float2*)(sbias + c0);
    int y = y0 + py;
#pragma unroll
    for (int p = 0; p < 8; p++) {
        float lo, hi; f2unpack(acc[p], lo, hi);
        float2 o;
        o.x = fmaxf(lo + bb.x, 0.f);
        o.y = fmaxf(hi + bb.y, 0.f);
        *(float2*)(g_x1 + ((size_t)(b * 256 + y) * 256 + (x0 + p)) * 64 + c0) = o;
    }
}

// ---------------- conv2: 3x3 s2, 64->256, relu; ci-pair packed ----------------
__global__ void __launch_bounds__(256, 2) conv2_kernel(const float* __restrict__ b2) {
    __shared__ __align__(16) float sm[9 * 17 * 64];
    int x0 = blockIdx.x * 8, y0 = blockIdx.y * 4, b = blockIdx.z;
    int t = threadIdx.x;
    for (int e = t; e < 9 * 17 * 64; e += 256) {
        int ci = e & 63; int rc = e >> 6; int c = rc % 17; int r = rc / 17;
        int iy = 2 * y0 + r, ix = 2 * x0 + c;
        float v = 0.f;
        if (iy < 256 && ix < 256) v = g_x1[((size_t)(b * 256 + iy) * 256 + ix) * 64 + ci];
        sm[e] = v;
    }
    __syncthreads();
    int co4 = t & 63, ry = t >> 6;
    u64 acc[8][4];
#pragma unroll
    for (int p = 0; p < 8; p++)
#pragma unroll
        for (int j = 0; j < 4; j++) acc[p][j] = 0ull;
    const u64* wt2d = (const u64*)g_wt2;
#pragma unroll
    for (int ky = 0; ky < 3; ky++) {
        int r = 2 * ry + ky;
#pragma unroll
        for (int kx = 0; kx < 3; kx++) {
            const float* sbase = sm + (r * 17 + kx) * 64;
            const u64* wb = wt2d + (size_t)((ky * 3 + kx) * 32) * 256 + co4 * 4;
            for (int ci2 = 0; ci2 < 32; ci2++) {
                u64 v[8];
#pragma unroll
                for (int p = 0; p < 8; p++) v[p] = *(const u64*)(sbase + p * 128 + 2 * ci2);
                ulonglong2 wA = *(const ulonglong2*)(wb + (size_t)ci2 * 256);
                ulonglong2 wB = *(const ulonglong2*)(wb + (size_t)ci2 * 256 + 2);
#pragma unroll
                for (int p = 0; p < 8; p++) {
                    ffma2(acc[p][0], v[p], wA.x);
                    ffma2(acc[p][1], v[p], wA.y);
                    ffma2(acc[p][2], v[p], wB.x);
                    ffma2(acc[p][3], v[p], wB.y);
                }
            }
        }
    }
    int y = y0 + ry;
    float4 bb = *(const float4*)(b2 + co4 * 4);
#pragma unroll
    for (int p = 0; p < 8; p++) {
        float4 o;
        o.x = fmaxf(f2sum(acc[p][0]) + bb.x, 0.f);
        o.y = fmaxf(f2sum(acc[p][1]) + bb.y, 0.f);
        o.z = fmaxf(f2sum(acc[p][2]) + bb.z, 0.f);
        o.w = fmaxf(f2sum(acc[p][3]) + bb.w, 0.f);
        *(float4*)(g_feat + ((size_t)(b * 128 + y) * 128 + (x0 + p)) * 256 + co4 * 4) = o;
    }
}

// ---------------- detection heads: ci-pair packed; all 3 outputs share feature loads ----------------
__global__ void heads_kernel(const float* __restrict__ bsc, const float* __restrict__ brg) {
    int b = blockIdx.y;
    int warp = threadIdx.x >> 5, lane = threadIdx.x & 31;
    int p = blockIdx.x * 8 + warp;
    int y = p >> 7, x = p & 127;
    u64 aS = 0ull, aY = 0ull, aX = 0ull;
    const u64* whd = (const u64*)g_wt_h;
#pragma unroll
    for (int ky = 0; ky < 3; ky++) {
        int iy = y + ky - 1; if ((unsigned)iy >= 128u) continue;
#pragma unroll
        for (int kx = 0; kx < 3; kx++) {
            int ix = x + kx - 1; if ((unsigned)ix >= 128u) continue;
            const u64* fp = (const u64*)(g_feat + ((size_t)(b * 128 + iy) * 128 + ix) * 256);
            const u64* wp = whd + (ky * 3 + kx) * 128 * 3;
#pragma unroll
            for (int q = 0; q < 4; q++) {
                int ci2 = lane + q * 32;
                u64 f = fp[ci2];
                ffma2(aS, f, __ldg(wp + ci2 * 3));
                ffma2(aY, f, __ldg(wp + ci2 * 3 + 1));
                ffma2(aX, f, __ldg(wp + ci2 * 3 + 2));
            }
        }
    }
    float as = f2sum(aS), ay = f2sum(aY), ax = f2sum(aX);
#pragma unroll
    for (int o = 16; o > 0; o >>= 1) {
        as += __shfl_down_sync(~0u, as, o);
        ay += __shfl_down_sync(~0u, ay, o);
        ax += __shfl_down_sync(~0u, ax, o);
    }
    if (lane == 0) {
        g_scores[b * 16384 + p] = sigmoidf(as + __ldg(bsc));
        g_reg[(b * 16384 + p) * 2]     = ay + __ldg(brg);
        g_reg[(b * 16384 + p) * 2 + 1] = ax + __ldg(brg + 1);
    }
}

// ---------------- fused seg (1x1 256->256 relu) + segr (1x1 256->32 relu); ci-pair packed ----------------
__global__ void __launch_bounds__(256, 2) segseg_kernel(const float* __restrict__ bseg,
                                                        const float* __restrict__ br) {
    __shared__ __align__(16) float sf[32 * 256];
    int b = blockIdx.y; int p0 = blockIdx.x * 32; int t = threadIdx.x;
    {
        const float4* src = (const float4*)(g_feat + ((size_t)b * 16384 + p0) * 256);
        float4* dst4 = (float4*)sf;
        for (int e = t; e < 2048; e += 256) dst4[e] = src[e];
    }
    __syncthreads();
    int cg = t & 63, pg = t >> 6;
    int c0 = cg * 4;
    const float* sbase = sf + pg * 8 * 256;
    u64 acc[8][4];
#pragma unroll
    for (int p = 0; p < 8; p++)
#pragma unroll
        for (int j = 0; j < 4; j++) acc[p][j] = 0ull;
    const u64* wtd = (const u64*)g_wt_seg + c0;
    for (int ci2 = 0; ci2 < 128; ci2++) {
        u64 v[8];
#pragma unroll
        for (int p = 0; p < 8; p++) v[p] = *(const u64*)(sbase + p * 256 + 2 * ci2);
        ulonglong2 wA = *(const ulonglong2*)(wtd + (size_t)ci2 * 256);
        ulonglong2 wB = *(const ulonglong2*)(wtd + (size_t)ci2 * 256 + 2);
#pragma unroll
        for (int p = 0; p < 8; p++) {
            ffma2(acc[p][0], v[p], wA.x);
            ffma2(acc[p][1], v[p], wA.y);
            ffma2(acc[p][2], v[p], wB.x);
            ffma2(acc[p][3], v[p], wB.y);
        }
    }
    float bs[4];
#pragma unroll
    for (int j = 0; j < 4; j++) bs[j] = __ldg(bseg + c0 + j);
    __syncthreads();
#pragma unroll
    for (int p = 0; p < 8; p++) {
        float4 o;
        o.x = fmaxf(f2sum(acc[p][0]) + bs[0], 0.f);
        o.y = fmaxf(f2sum(acc[p][1]) + bs[1], 0.f);
        o.z = fmaxf(f2sum(acc[p][2]) + bs[2], 0.f);
        o.w = fmaxf(f2sum(acc[p][3]) + bs[3], 0.f);
        *(float4*)(sf + (pg * 8 + p) * 256 + c0) = o;
    }
    __syncthreads();
    int co = t & 31, pg2 = t >> 5;
    u64 a2[4];
#pragma unroll
    for (int q = 0; q < 4; q++) a2[q] = 0ull;
    const u64* wrd = (const u64*)g_wt_r + co;
    const float* s2 = sf + pg2 * 4 * 256;
    for (int ci2 = 0; ci2 < 128; ci2++) {
        u64 w = wrd[ci2 * 32];
#pragma unroll
        for (int q = 0; q < 4; q++)
            ffma2(a2[q], *(const u64*)(s2 + q * 256 + 2 * ci2), w);
    }
    float bc = __ldg(br + co);
#pragma unroll
    for (int q = 0; q < 4; q++)
        g_segr[((size_t)b * 16384 + p0 + pg2 * 4 + q) * 32 + co] = fmaxf(f2sum(a2[q]) + bc, 0.f);
}

// ---------------- top-K_PRE: full bitonic sort of 16384 packed keys per batch ----------------
__global__ void topk_kernel() {
    extern __shared__ unsigned long long sk[];
    int b = blockIdx.x, t = threadIdx.x;
    for (int e = t; e < 16384; e += 1024) {
        unsigned fb = __float_as_uint(g_scores[b * 16384 + e]);
        sk[e] = ((unsigned long long)fb << 32) | (unsigned)(16383 - e);
    }
    for (unsigned k = 2; k <= 16384u; k <<= 1)
        for (unsigned j = k >> 1; j > 0; j >>= 1) {
            __syncthreads();
            for (unsigned e = t; e < 16384; e += 1024) {
                unsigned l = e ^ j;
                if (l > e) {
                    unsigned long long A = sk[e], C = sk[l];
                    bool desc = ((e & k) == 0);
                    if ((A < C) == desc) { sk[e] = C; sk[l] = A; }
                }
            }
        }
    __syncthreads();
    for (int e = t; e < KPRE; e += 1024) {
        unsigned long long key = sk[e];
        float s = __uint_as_float((unsigned)(key >> 32));
        int idx = 16383 - (int)(unsigned)(key & 0xFFFFFFFFu);
        g_topsc[b * KPRE + e] = s;
        float yy = (float)(idx >> 7), xx = (float)(idx & 127);
        g_locs[(b * KPRE + e) * 2]     = yy + 0.5f + g_reg[(b * 16384 + idx) * 2];
        g_locs[(b * KPRE + e) * 2 + 1] = xx + 0.5f + g_reg[(b * 16384 + idx) * 2 + 1];
    }
}

// ---------------- suppression bitmatrix: sup[i] bit j <=> dist(i,j) <= 1.1 ----------------
__global__ void sup_kernel() {
    int i = blockIdx.x, b = blockIdx.y, w = threadIdx.x;   // 64 threads
    float ly = g_locs[(b * KPRE + i) * 2], lx = g_locs[(b * KPRE + i) * 2 + 1];
    unsigned bits = 0;
    if (w < 63) {
        int j0 = w * 32;
#pragma unroll 4
        for (int u = 0; u < 32; u++) {
            int j = j0 + u;
            if (j < KPRE) {
                float dy = ly - g_locs[(b * KPRE + j) * 2];
                float dx = lx - g_locs[(b * KPRE + j) * 2 + 1];
                if (sqrtf(dy * dy + dx * dx) <= 1.1f) bits |= (1u << u);
            }
        }
    }
    g_sup[((size_t)(b * KPRE) + i) * 64 + w] = bits;
}

// ---------------- sequential greedy NMS scan (single warp/batch, deep prefetch) ----------------
__global__ void nms_scan_kernel() {
    int b = blockIdx.x, lane = threadIdx.x;   // 32 threads
    __shared__ unsigned ssup[64];
    __shared__ int slist[KOUT];
    ssup[lane] = 0; ssup[lane + 32] = 0;
    __syncwarp();
    const unsigned* base = g_sup + (size_t)b * KPRE * 64;
    unsigned ca[8], cb[8], na[8], nb[8];
#pragma unroll
    for (int u = 0; u < 8; u++) {
        ca[u] = base[(size_t)u * 64 + lane];
        cb[u] = (lane < 31) ? base[(size_t)u * 64 + 32 + lane] : 0u;
    }
    int cnt = 0;
    for (int ch = 0; ch < KPRE; ch += 8) {
        if (ch + 8 < KPRE) {
#pragma unroll
            for (int u = 0; u < 8; u++) {
                int i = ch + 8 + u;
                na[u] = base[(size_t)i * 64 + lane];
                nb[u] = (lane < 31) ? base[(size_t)i * 64 + 32 + lane] : 0u;
            }
        }
#pragma unroll
        for (int u = 0; u < 8; u++) {
            int i = ch + u;
            bool kp = ((ssup[i >> 5] >> (i & 31)) & 1u) == 0u;
            if (kp) {
                ssup[lane] |= ca[u];
                if (lane < 31) ssup[32 + lane] |= cb[u];
                if (lane == 0) { if (cnt < KOUT) slist[cnt] = i; cnt++; }
            }
            __syncwarp();
        }
#pragma unroll
        for (int u = 0; u < 8; u++) { ca[u] = na[u]; cb[u] = nb[u]; }
    }
    cnt = __shfl_sync(~0u, cnt, 0);
    if (lane == 0) g_nsel[b] = cnt;
    __syncwarp();
    int n = cnt < KOUT ? cnt : KOUT;
    for (int k = lane; k < n; k += 32) g_sel[b * KOUT + k] = slist[k];
}

// ---------------- selection: sel_s, pix outputs + crop top-lefts ----------------
__global__ void select_kernel(float* __restrict__ out) {
    int b = blockIdx.x; int k = threadIdx.x;
    if (k >= KOUT) return;
    int n = g_nsel[b]; if (n > KOUT) n = KOUT;
    bool valid = (k < n);
    float s = -1.f, ly = 0.f, lx = 0.f;
    if (valid) {
        int i = g_sel[b * KOUT + k];
        s  = g_topsc[b * KPRE + i];
        ly = g_locs[(b * KPRE + i) * 2];
        lx = g_locs[(b * KPRE + i) * 2 + 1];
    }
    float cy, cx;
    int o = b * KOUT + k;
    if (valid) {
        out[o] = s;
        out[2000 + o * 2]     = ly * 4.f;
        out[2000 + o * 2 + 1] = lx * 4.f;
        cy = ly; cx = lx;
    } else {
        out[o] = -1.f;
        out[2000 + o * 2] = -1.f;
        out[2000 + o * 2 + 1] = -1.f;
        cy = -0.25f; cx = -0.25f;    // pix=-1 -> (-1/512)*128
    }
    int ty = (int)rintf(cy) - 16; ty = min(max(ty, 0), 96);
    int tx = (int)rintf(cx) - 16; tx = min(max(tx, 0), 96);
    g_tl[o * 2] = ty; g_tl[o * 2 + 1] = tx;
}

// ---------------- inst_full: global 3x3 conv(32->32) over segr; weights direct from L1 ----------------
__global__ void instfull_kernel(const float* __restrict__ bp1v,
                                const float* __restrict__ wp2, const float* __restrict__ bp2v) {
    int t = threadIdx.x;
    int b = blockIdx.y;
    int warp = t >> 5, lane = t & 31;
    int p = blockIdx.x * 8 + warp;
    int y = p >> 7, x = p & 127;
    const u64* wsd = (const u64*)g_wt_p1;
    u64 accA = 0ull, accB = 0ull;
#pragma unroll
    for (int dy = -1; dy <= 1; dy++) {
        int iy = y + dy; if ((unsigned)iy >= 128u) continue;
#pragma unroll
        for (int dx = -1; dx <= 1; dx++) {
            int ix = x + dx; if ((unsigned)ix >= 128u) continue;
            const float* sp = g_segr + ((size_t)(b * 128 + iy) * 128 + ix) * 32;
            const u64* wb = wsd + (((dy + 1) * 3 + (dx + 1)) * 16) * 32 + lane;
#pragma unroll
            for (int ci2 = 0; ci2 < 16; ci2 += 2) {
                ffma2(accA, *(const u64*)(sp + 2 * ci2), __ldg(wb + ci2 * 32));
                ffma2(accB, *(const u64*)(sp + 2 * ci2 + 2), __ldg(wb + (ci2 + 1) * 32));
            }
        }
    }
    float a = f2sum2(accA, accB);
    g_acc1[((size_t)(b * 128 + y) * 128 + x) * 32 + lane] = a;
    float h = fmaxf(a + __ldg(bp1v + lane), 0.f);
    float v = h * __ldg(wp2 + lane);
#pragma unroll
    for (int o = 16; o > 0; o >>= 1) v += __shfl_down_sync(~0u, v, o);
    if (lane == 0) g_instfull[(size_t)(b * 128 + y) * 128 + x] = sigmoidf(v + __ldg(bp2v));
}

// ---------------- per-patch: gather interior; border via acc1 subtraction; no smem ----------------
__global__ void patch_kernel(const float* __restrict__ bp1v,
                             const float* __restrict__ wp2, const float* __restrict__ bp2v,
                             float* __restrict__ out) {
    int blk = blockIdx.x; int b = blk / KOUT, k = blk % KOUT;
    int t = threadIdx.x;
    int ty = g_tl[(b * KOUT + k) * 2], tx = g_tl[(b * KOUT + k) * 2 + 1];
    float* obase = out + 6000 + ((size_t)(b * KOUT + k)) * 1024;
    for (int e = t; e < 1024; e += 256) {
        int py = e >> 5, px = e & 31;
        if (py >= 1 && py <= 30 && px >= 1 && px <= 30)
            obase[e] = g_instfull[(size_t)(b * 128 + ty + py) * 128 + tx + px];
    }
    float bp2s = __ldg(bp2v);
    int warp = t >> 5, lane = t & 31;
    const u64* wsd = (const u64*)g_wt_p1;
    float sb1l = __ldg(bp1v + lane);
    float sw2l = __ldg(wp2 + lane);
    for (int bp = warp; bp < 124; bp += 8) {
        int py, px;
        if (bp < 32)      { py = 0;       px = bp; }
        else if (bp < 64) { py = 31;      px = bp - 32; }
        else if (bp < 94) { py = bp - 63; px = 0; }
        else              { py = bp - 93; px = 31; }
        int gy = ty + py, gx = tx + px;
        u64 corr = 0ull;
#pragma unroll
        for (int dy = -1; dy <= 1; dy++) {
            int ly = py + dy, yy = gy + dy;
#pragma unroll
            for (int dx = -1; dx <= 1; dx++) {
                int lx = px + dx, xx = gx + dx;
                bool outside_patch = ((unsigned)ly >= 32u) || ((unsigned)lx >= 32u);
                bool inside_global = ((unsigned)yy < 128u) && ((unsigned)xx < 128u);
                if (outside_patch && inside_global) {
                    const float* sp = g_segr + ((size_t)(b * 128 + yy) * 128 + xx) * 32;
                    const u64* wb = wsd + (((dy + 1) * 3 + (dx + 1)) * 16) * 32 + lane;
#pragma unroll
                    for (int ci2 = 0; ci2 < 16; ci2++)
                        ffma2(corr, *(const u64*)(sp + 2 * ci2), __ldg(wb + ci2 * 32));
                }
            }
        }
        float a = g_acc1[((size_t)(b * 128 + gy) * 128 + gx) * 32 + lane] - f2sum(corr);
        float h = fmaxf(a + sb1l, 0.f);
        float v = h * sw2l;
#pragma unroll
        for (int o = 16; o > 0; o >>= 1) v += __shfl_down_sync(~0u, v, o);
        if (lane == 0) obase[py * 32 + px] = sigmoidf(v + bp2s);
    }
}

// ---------------- launch ----------------
extern "C" void kernel_launch(void* const* d_in, const int* in_sizes, int n_in,
                              void* d_out, int out_size) {
    const float* image = (const float*)d_in[0];
    const float* w1   = (const float*)d_in[1];
    const float* b1   = (const float*)d_in[2];
    const float* w2   = (const float*)d_in[3];
    const float* b2   = (const float*)d_in[4];
    const float* wseg = (const float*)d_in[5];
    const float* bseg = (const float*)d_in[6];
    const float* wsc  = (const float*)d_in[7];
    const float* bsc  = (const float*)d_in[8];
    const float* wrg  = (const float*)d_in[9];
    const float* brg  = (const float*)d_in[10];
    const float* wr   = (const float*)d_in[11];
    const float* br   = (const float*)d_in[12];
    const float* wp1  = (const float*)d_in[13];
    const float* bp1  = (const float*)d_in[14];
    const float* wp2  = (const float*)d_in[15];
    const float* bp2  = (const float*)d_in[16];
    float* out = (float*)d_out;

    cudaFuncSetAttribute(topk_kernel, cudaFuncAttributeMaxDynamicSharedMemorySize, 131072);

    tr_seg_kernel<<<256, 256>>>(wseg);
    tr_r_kernel<<<32, 256>>>(wr);
    tr_w2_kernel<<<576, 256>>>(w2);
    tr_h_kernel<<<27, 256>>>(wsc, wrg);
    tr_p1_kernel<<<36, 256>>>(wp1);

    conv1_kernel<<<dim3(32, 32, 4), 256>>>(image, w1, b1);
    conv2_kernel<<<dim3(16, 32, 4), 256>>>(b2);
    heads_kernel<<<dim3(2048, 4), 256>>>(bsc, brg);
    segseg_kernel<<<dim3(512, 4), 256>>>(bseg, br);
    topk_kernel<<<4, 1024, 131072>>>();
    sup_kernel<<<dim3(KPRE, 4), 64>>>();
    nms_scan_kernel<<<4, 32>>>();
    select_kernel<<<4, 512>>>(out);
    instfull_kernel<<<dim3(2048, 4), 256>>>(bp1, wp2, bp2);
    patch_kernel<<<BB * KOUT, 256>>>(bp1, wp2, bp2, out);
}